// round 7
// baseline (speedup 1.0000x reference)
#include <cuda_runtime.h>
#include <cuda_bf16.h>

// PatchConsistencyLoss: structure [32,32,32,32] int32, patch 4x4x4 -> 16384 patches x 64 voxels.
// Per patch: entropy of non-air token histogram; mean over patches.
//
// R5: 1 warp/patch, 2 voxels/lane (va=idx t, vb=idx t+32 = +2048 gmem).
//  - intra-set pair info: 2x __match_any_sync
//  - cross-set pair info: 4x __match_any_sync over half/half lane splits (no SMEM sweep)
//  - unique-token representative: va-side first occurrence; vb emits only if token absent from va
//  - warp shuffle reduce; fused final reduction via last-block-done (deterministic order)

#define NPATCH 16384
#define WPB 8                  // warps (=patches) per 256-thread block
#define NBLK (NPATCH / WPB)    // 2048

__device__ float g_partial[NBLK];
__device__ int   g_ctr = 0;

__global__ __launch_bounds__(256, 8)
void patch_entropy_fused(const int* __restrict__ s, float* __restrict__ out) {
    __shared__ float warp_sums[WPB];
    __shared__ double sd[256];
    __shared__ int s_last;

    const int tid  = threadIdx.x;
    const int w    = tid >> 5;
    const int lane = tid & 31;
    const int p    = blockIdx.x * WPB + w;

    // p = ((b*8 + pd)*8 + ph)*8 + pw
    const int b  = p >> 9;
    const int r  = p & 511;
    const int pd = r >> 6;
    const int ph = (r >> 3) & 7;
    const int pw = r & 7;

    // voxel t (0..31): dz=t>>4, dy=(t>>2)&3, dx=t&3 ; t+32 adds 2 to dz -> +2048 elements
    const int idx = (b << 15) + (pd << 12) + (ph << 7) + (pw << 2)
                  + ((lane >> 4) << 10) + (((lane >> 2) & 3) << 5) + (lane & 3);

    const int va = s[idx];
    const int vb = s[idx + 2048];

    const bool aa = (va == 102) | (va == 576) | (va == 3352);
    const bool ab = (vb == 102) | (vb == 576) | (vb == 3352);

    const unsigned full = 0xffffffffu;
    const bool lo = lane < 16;

    // intra-set equality (all 32x32 pairs each, 1 instr each)
    const unsigned ma = __match_any_sync(full, va);
    const unsigned mb = __match_any_sync(full, vb);

    const int tot = __popc(__ballot_sync(full, !aa)) + __popc(__ballot_sync(full, !ab));

    // cross-set equality via 4 half/half matches.
    // vbx = partner half's vb (lane l<16 holds vb[l+16], lane l>=16 holds vb[l-16])
    const int vbx = __shfl_xor_sync(full, vb, 16);
    const unsigned mA = __match_any_sync(full, lo ? va  : vbx); // va_lo x vb_lo
    const unsigned mB = __match_any_sync(full, lo ? va  : vb ); // va_lo x vb_hi
    const unsigned mC = __match_any_sync(full, lo ? vb  : va ); // va_hi x vb_lo
    const unsigned mD = __match_any_sync(full, lo ? vbx : va ); // va_hi x vb_hi

    // cab = #{ j : vb[j] == va[lane] }  (resident on the va owner's lane)
    const int cab = lo ? (__popc(mA >> 16) + __popc(mB >> 16))
                       : (__popc(mC & 0xFFFFu) + __popc(mD & 0xFFFFu));

    // exist_ba = any(va == vb[lane]); one half computed locally, other half on partner lane
    const int eLocal  = lo ? ((mC >> 16) != 0u)      : ((mB & 0xFFFFu) != 0u);
    const int eForPtr = lo ? ((mD >> 16) != 0u)      : ((mA & 0xFFFFu) != 0u); // for partner's vb
    const int exist_ba = eLocal | __shfl_xor_sync(full, eForPtr, 16);

    const unsigned lt = (1u << lane) - 1u;
    const float rtot = __fdividef(1.0f, (float)tot);  // tot>=1 whenever an emit happens
    float term = 0.0f;
    if (!aa && (ma & lt) == 0) {                       // va-side representative
        const float pr = (float)(__popc(ma) + cab) * rtot;
        term -= pr * __logf(pr + 1e-10f);
    }
    if (!ab && (mb & lt) == 0 && !exist_ba) {          // vb-only token representative
        const float pr = (float)__popc(mb) * rtot;
        term -= pr * __logf(pr + 1e-10f);
    }

    // warp reduce (fixed butterfly -> deterministic)
    #pragma unroll
    for (int o = 16; o > 0; o >>= 1)
        term += __shfl_xor_sync(full, term, o);
    if (lane == 0) warp_sums[w] = term;
    __syncthreads();

    if (tid == 0) {
        float bs = 0.0f;
        #pragma unroll
        for (int i = 0; i < WPB; i++) bs += warp_sums[i];
        g_partial[blockIdx.x] = bs;
        __threadfence();
        const int old = atomicAdd(&g_ctr, 1);
        s_last = (old == NBLK - 1);
    }
    __syncthreads();

    if (s_last) {
        __threadfence();
        double acc = 0.0;
        #pragma unroll
        for (int i = tid; i < NBLK; i += 256) acc += (double)g_partial[i];
        sd[tid] = acc;
        __syncthreads();
        #pragma unroll
        for (int off = 128; off > 0; off >>= 1) {
            if (tid < off) sd[tid] += sd[tid + off];
            __syncthreads();
        }
        if (tid == 0) {
            out[0] = (float)(sd[0] / (16384.0 + 1e-6));
            g_ctr = 0;   // graph-replay safe reset
        }
    }
}

extern "C" void kernel_launch(void* const* d_in, const int* in_sizes, int n_in,
                              void* d_out, int out_size) {
    const int* structure = (const int*)d_in[0];
    float* out = (float*)d_out;
    patch_entropy_fused<<<NBLK, 256>>>(structure, out);
}